// round 2
// baseline (speedup 1.0000x reference)
#include <cuda_runtime.h>

// DempsterSchaferCombine — algebraically reduced to a pure elementwise stream:
//   out = (a1-1)*(a2-1)/21 + a1 + a2 - 1
// (Dirichlet strengths S1,S2 and the conflict denom cancel exactly.)
//
// R2: persistent grid-stride, 4x float4 per thread per iteration with
// front-batched loads (MLP_p1 = 8 LDG.128 per thread) + streaming cache
// hints (.cs) since there is zero reuse.

#define INV_C (1.0f / 21.0f)

__device__ __forceinline__ float4 ds4(float4 x, float4 y) {
    float4 r;
    r.x = fmaf((x.x - 1.0f) * (y.x - 1.0f), INV_C, x.x + y.x - 1.0f);
    r.y = fmaf((x.y - 1.0f) * (y.y - 1.0f), INV_C, x.y + y.y - 1.0f);
    r.z = fmaf((x.z - 1.0f) * (y.z - 1.0f), INV_C, x.z + y.z - 1.0f);
    r.w = fmaf((x.w - 1.0f) * (y.w - 1.0f), INV_C, x.w + y.w - 1.0f);
    return r;
}

__global__ __launch_bounds__(256) void ds_combine_kernel(
    const float4* __restrict__ a1,
    const float4* __restrict__ a2,
    float4* __restrict__ out,
    int n4)
{
    const int tid    = blockIdx.x * blockDim.x + threadIdx.x;
    const int nthr   = gridDim.x * blockDim.x;
    const int stride = nthr;            // contiguous within each batch slot

    // Main loop: 4 float4 per thread per iteration, loads front-batched.
    int i = tid;
    const int n4_main = n4 - 3 * stride; // last full-quad start bound
    for (; i < n4_main; i += 4 * stride) {
        float4 x0 = __ldcs(a1 + i);
        float4 x1 = __ldcs(a1 + i + stride);
        float4 x2 = __ldcs(a1 + i + 2 * stride);
        float4 x3 = __ldcs(a1 + i + 3 * stride);
        float4 y0 = __ldcs(a2 + i);
        float4 y1 = __ldcs(a2 + i + stride);
        float4 y2 = __ldcs(a2 + i + 2 * stride);
        float4 y3 = __ldcs(a2 + i + 3 * stride);

        __stcs(out + i,              ds4(x0, y0));
        __stcs(out + i + stride,     ds4(x1, y1));
        __stcs(out + i + 2 * stride, ds4(x2, y2));
        __stcs(out + i + 3 * stride, ds4(x3, y3));
    }
    // Remainder (fewer than 4 strides left)
    for (; i < n4; i += stride) {
        float4 x = __ldcs(a1 + i);
        float4 y = __ldcs(a2 + i);
        __stcs(out + i, ds4(x, y));
    }
}

// Scalar tail for n % 4 != 0 (not hit for this shape; kept for safety).
__global__ void ds_combine_tail(
    const float* __restrict__ a1,
    const float* __restrict__ a2,
    float* __restrict__ out,
    int start, int n)
{
    int i = start + blockIdx.x * blockDim.x + threadIdx.x;
    if (i >= n) return;
    float x = a1[i], y = a2[i];
    out[i] = fmaf((x - 1.0f) * (y - 1.0f), INV_C, x + y - 1.0f);
}

extern "C" void kernel_launch(void* const* d_in, const int* in_sizes, int n_in,
                              void* d_out, int out_size)
{
    const float* a1 = (const float*)d_in[0];
    const float* a2 = (const float*)d_in[1];
    float* out = (float*)d_out;

    int n = out_size;          // 8*21*512*512 = 44,040,192
    int n4 = n >> 2;           // 11,010,048 float4 (divisible)

    // GB300: 152 SMs; 8 blocks/SM at 256 thr (occupancy-limited by warps).
    const int threads = 256;
    const int blocks = 152 * 8;   // 1216 persistent blocks, ~36 quads/thread

    ds_combine_kernel<<<blocks, threads>>>(
        (const float4*)a1, (const float4*)a2, (float4*)out, n4);

    int tail_start = n4 << 2;
    if (n - tail_start > 0) {
        ds_combine_tail<<<1, 128>>>(a1, a2, out, tail_start, n);
    }
}

// round 3
// speedup vs baseline: 1.0559x; 1.0559x over previous
#include <cuda_runtime.h>

// DempsterSchaferCombine — algebraically reduced to a pure elementwise stream:
//   out = (a1-1)*(a2-1)/21 + a1 + a2 - 1
// (Dirichlet strengths S1,S2 and the conflict denom cancel exactly.)
//
// R3: one-shot grid, 2 block-contiguous float4 per thread (4 independent
// LDG.128 front-batched), regs capped at 32 via __launch_bounds__(256,8)
// so occupancy stays at 2048 thr/SM. .cs hints (zero reuse).

#define INV_C (1.0f / 21.0f)

__device__ __forceinline__ float4 ds4(float4 x, float4 y) {
    float4 r;
    r.x = fmaf((x.x - 1.0f) * (y.x - 1.0f), INV_C, x.x + y.x - 1.0f);
    r.y = fmaf((x.y - 1.0f) * (y.y - 1.0f), INV_C, x.y + y.y - 1.0f);
    r.z = fmaf((x.z - 1.0f) * (y.z - 1.0f), INV_C, x.z + y.z - 1.0f);
    r.w = fmaf((x.w - 1.0f) * (y.w - 1.0f), INV_C, x.w + y.w - 1.0f);
    return r;
}

__global__ __launch_bounds__(256, 8) void ds_combine_kernel(
    const float4* __restrict__ a1,
    const float4* __restrict__ a2,
    float4* __restrict__ out,
    int n4)
{
    // Each block covers 512 contiguous float4: [base, base+512)
    int base = blockIdx.x * 512 + threadIdx.x;
    int i0 = base;
    int i1 = base + 256;

    if (i1 < n4) {
        // Fast path: both elements in range; 4 independent loads up front.
        float4 x0 = __ldcs(a1 + i0);
        float4 x1 = __ldcs(a1 + i1);
        float4 y0 = __ldcs(a2 + i0);
        float4 y1 = __ldcs(a2 + i1);
        __stcs(out + i0, ds4(x0, y0));
        __stcs(out + i1, ds4(x1, y1));
    } else if (i0 < n4) {
        float4 x0 = __ldcs(a1 + i0);
        float4 y0 = __ldcs(a2 + i0);
        __stcs(out + i0, ds4(x0, y0));
    }
}

// Scalar tail for n % 4 != 0 (not hit for this shape; kept for safety).
__global__ void ds_combine_tail(
    const float* __restrict__ a1,
    const float* __restrict__ a2,
    float* __restrict__ out,
    int start, int n)
{
    int i = start + blockIdx.x * blockDim.x + threadIdx.x;
    if (i >= n) return;
    float x = a1[i], y = a2[i];
    out[i] = fmaf((x - 1.0f) * (y - 1.0f), INV_C, x + y - 1.0f);
}

extern "C" void kernel_launch(void* const* d_in, const int* in_sizes, int n_in,
                              void* d_out, int out_size)
{
    const float* a1 = (const float*)d_in[0];
    const float* a2 = (const float*)d_in[1];
    float* out = (float*)d_out;

    int n = out_size;          // 8*21*512*512 = 44,040,192
    int n4 = n >> 2;           // 11,010,048 float4

    const int threads = 256;
    const int f4_per_block = 512;
    int blocks = (n4 + f4_per_block - 1) / f4_per_block;   // 21504

    ds_combine_kernel<<<blocks, threads>>>(
        (const float4*)a1, (const float4*)a2, (float4*)out, n4);

    int tail_start = n4 << 2;
    if (n - tail_start > 0) {
        ds_combine_tail<<<1, 128>>>(a1, a2, out, tail_start, n);
    }
}